// round 14
// baseline (speedup 1.0000x reference)
#include <cuda_runtime.h>
#include <cuda_fp16.h>
#include <stdint.h>

// ---------------------------------------------------------------------------
// Problem constants
// ---------------------------------------------------------------------------
#define N_TOK 65536
#define DIM   1024
#define S_SEM 200
#define NPACK 352      // 1 cls + 12 fused-sem + 324 bbox + 15 zero pad
#define NSC   81
#define NBB   324
#define BK    64
#define NKCH  (DIM / BK)     // 16
#define THREADS 512

// Heterogeneous tiling: 444 tiles of 128 rows (3 exact waves on 148 SMs),
// then 136 tiles of 64 rows (~0.5 wave at half duration).
#define NBIG   444
#define BIGROWS  (NBIG * 128)        // 56832
#define NSMALL 136                    // (65536-56832)/64
#define GRID   (NBIG + NSMALL)        // 580

// Packed fp16 weights + fp32 bias (built by prep kernel every launch)
__device__ __half g_Wp[NPACK * DIM];
__device__ float  g_bp[NPACK];

// Selected class indices (0-based into the 80 class cols): {i-1 : i in IGNORE2} U {79}
__constant__ int c_sel[12] = {1, 2, 16, 18, 29, 37, 47, 53, 63, 68, 72, 79};

__device__ __forceinline__ uint32_t smem_u32(const void* p) {
    uint32_t a;
    asm("{ .reg .u64 t; cvta.to.shared.u64 t, %1; cvt.u32.u64 %0, t; }"
        : "=r"(a) : "l"(p));
    return a;
}

// ---------------------------------------------------------------------------
// SMEM layout (bytes). GEMM region overlaid by epilogue staging.
// A16: DOUBLE buffered fp16 tile (128 x 128B each). No A32 staging buffer.
// ---------------------------------------------------------------------------
#define SMO_BIAS 0                                // 1536
#define SMO_A16  1536                             // 2 x 128 x 128B = 32768
#define SMO_B    (SMO_A16 + 2 * 128 * 128)        // 34304; 2 x 352 x 128B = 90112
#define SMO_STAGE 1536
#define STRIDE_W 412
#define SM_TOTAL (SMO_STAGE + 128 * STRIDE_W * 4) // 212480

// ---------------------------------------------------------------------------
// Prep: pack [W_cls ; sem_matrix[sel] @ W_sem / S ; W_bbox ; 0-pad] -> fp16
// ---------------------------------------------------------------------------
#define SEM_BLKS 48
__global__ void prep_kernel(const float* __restrict__ W_cls,
                            const float* __restrict__ b_cls,
                            const float* __restrict__ W_sem,
                            const float* __restrict__ b_sem,
                            const float* __restrict__ W_bbox,
                            const float* __restrict__ b_bbox,
                            const float* __restrict__ sem_m) {
    const int tid = threadIdx.x;
    const int bid = blockIdx.x;
    if (bid < SEM_BLKS) {
        __shared__ float sM[S_SEM];
        const int r = (bid >> 2) + 1;            // packed row 1..12
        const int chunk = bid & 3;
        const int sj = c_sel[r - 1];
        const float* M = sem_m + (size_t)sj * S_SEM;
        if (tid < S_SEM) sM[tid] = M[tid];
        __syncthreads();
        const int d = chunk * 256 + tid;
        const float* Wcol = W_sem + d;
        float a0 = 0.f, a1 = 0.f, a2 = 0.f, a3 = 0.f;
        float a4 = 0.f, a5 = 0.f, a6 = 0.f, a7 = 0.f;
#pragma unroll 5
        for (int s = 0; s < S_SEM; s += 8) {
            a0 += sM[s + 0] * __ldg(Wcol + (size_t)(s + 0) * DIM);
            a1 += sM[s + 1] * __ldg(Wcol + (size_t)(s + 1) * DIM);
            a2 += sM[s + 2] * __ldg(Wcol + (size_t)(s + 2) * DIM);
            a3 += sM[s + 3] * __ldg(Wcol + (size_t)(s + 3) * DIM);
            a4 += sM[s + 4] * __ldg(Wcol + (size_t)(s + 4) * DIM);
            a5 += sM[s + 5] * __ldg(Wcol + (size_t)(s + 5) * DIM);
            a6 += sM[s + 6] * __ldg(Wcol + (size_t)(s + 6) * DIM);
            a7 += sM[s + 7] * __ldg(Wcol + (size_t)(s + 7) * DIM);
        }
        float acc = ((a0 + a1) + (a2 + a3)) + ((a4 + a5) + (a6 + a7));
        g_Wp[(size_t)r * DIM + d] = __float2half(acc * (1.0f / S_SEM));
        if (chunk == 0 && tid < 32) {
            float p = 0.f;
            for (int s = tid; s < S_SEM; s += 32) p += sM[s] * b_sem[s];
#pragma unroll
            for (int o = 16; o > 0; o >>= 1) p += __shfl_xor_sync(0xffffffffu, p, o);
            if (tid == 0) g_bp[r] = p * (1.0f / S_SEM);
        }
    } else {
        const int r = bid - SEM_BLKS;            // 0..351
        if (r >= 1 && r <= 12) return;           // sem blocks own these
        __half* dst = g_Wp + (size_t)r * DIM;
        if (r == 0) {
            float4 v = ((const float4*)W_cls)[tid];
            ((__half2*)dst)[tid * 2 + 0] = __floats2half2_rn(v.x, v.y);
            ((__half2*)dst)[tid * 2 + 1] = __floats2half2_rn(v.z, v.w);
            if (tid == 0) g_bp[0] = b_cls[0];
        } else if (r < 13 + NBB) {
            const int c = r - 13;
            float4 v = ((const float4*)(W_bbox + (size_t)c * DIM))[tid];
            ((__half2*)dst)[tid * 2 + 0] = __floats2half2_rn(v.x, v.y);
            ((__half2*)dst)[tid * 2 + 1] = __floats2half2_rn(v.z, v.w);
            if (tid == 0) g_bp[r] = b_bbox[c];
        } else {
            ((__half2*)dst)[tid * 2 + 0] = __floats2half2_rn(0.f, 0.f);
            ((__half2*)dst)[tid * 2 + 1] = __floats2half2_rn(0.f, 0.f);
            if (tid == 0) g_bp[r] = 0.0f;
        }
    }
}

// ---------------------------------------------------------------------------
// Main GEMM. bid < NBIG: [128,1024]x[1024,352] tile; else [64,...] tail tile.
// 16 warps = 4M x 4N; warp tile (16*nmf) x 88; nmf = 2 (big) or 1 (small).
// Schedule per kc (ONE barrier, no serial convert phase):
//   stageB(kc+1) -> { per ks: LDG A(kc+1) piece ... MMA(kc) ... STS A16(kc+1) }
//   -> wait_group 0 -> bar
// A16 double buffered: in-phase writes hit (kc+1)&1, MMA reads kc&1;
// previous reader of (kc+1)&1 (= MMA(kc-1)) fenced by the phase barrier.
// ---------------------------------------------------------------------------
__global__ void __launch_bounds__(THREADS, 1)
fpn_gemm(const float* __restrict__ x, float* __restrict__ out) {
    extern __shared__ char smem[];
    float* s_bias = (float*)(smem + SMO_BIAS);
    float* s_stage = (float*)(smem + SMO_STAGE);
    const uint32_t sbA16 = smem_u32(smem + SMO_A16);
    const uint32_t sbB   = smem_u32(smem + SMO_B);

    const int tid = threadIdx.x;
    const int wid = tid >> 5, lid = tid & 31;
    const int wm = wid >> 2, wn = wid & 3;        // 4 warps M x 4 warps N
    const int bid = blockIdx.x;
    const bool big = bid < NBIG;
    const int mbase = big ? bid * 128 : BIGROWS + (bid - NBIG) * 64;
    const int arows = big ? 128 : 64;             // tile rows
    const int nmf   = big ? 2 : 1;                // m-frags per warp
    const int q = lid >> 2, t = lid & 3;

    for (int i = tid; i < NPACK; i += THREADS) s_bias[i] = g_bp[i];

    float acc[2][11][4];
#pragma unroll
    for (int a = 0; a < 2; a++)
#pragma unroll
        for (int b = 0; b < 11; b++)
#pragma unroll
            for (int e = 0; e < 4; e++) acc[a][b][e] = 0.0f;

    // A convert coordinates: each thread owns row a_r; float4 unit (a_j + 4*ks)
    // of the 16 float4s in a 64-float row. One float4 -> 8 bytes fp16 (uint2).
    const int a_r = tid >> 2;            // 0..127
    const int a_j = tid & 3;             // 0..3
    const bool a_on = a_r < arows;

    // Convert one float4 of chunk kc into A16[kc&1] (SW128 swizzled).
    // Byte offset: 8 bytes per float4 unit -> (a_j + 4*ks) * 8, range 0..120.
    auto cvtA = [&](int kc, int ks, float4 v) {
        union { __half2 h[2]; uint2 u; } p;
        p.h[0] = __floats2half2_rn(v.x, v.y);
        p.h[1] = __floats2half2_rn(v.z, v.w);
        uint32_t off = (uint32_t)(a_r * 128 + (a_j + 4 * ks) * 8);
        *(uint2*)(smem + SMO_A16 + (kc & 1) * 16384 + (off ^ ((off >> 3) & 0x70))) = p.u;
    };
    auto ldgA = [&](int kc, int ks) -> float4 {
        return __ldg((const float4*)(x + (size_t)(mbase + a_r) * DIM + kc * BK)
                     + a_j + 4 * ks);
    };

    // --- B stage (cp.async, double buffer) ---
    auto stageB = [&](int kc) {
        if (kc < NKCH) {
            const char* ws = (const char*)g_Wp + (size_t)kc * (BK * 2);
            const uint32_t bdst = sbB + (kc & 1) * (NPACK * 128);
#pragma unroll
            for (int it = 0; it < 6; it++) {
                int i = it * THREADS + tid;          // 0..2815 (guarded)
                if (it < 5 || i < NPACK * 8) {
                    int r = i >> 3, j = i & 7;
                    uint32_t off = (uint32_t)(r * 128 + j * 16);
                    uint32_t d = bdst + (off ^ ((off >> 3) & 0x70));
                    const char* s = ws + (size_t)r * (DIM * 2) + j * 16;
                    asm volatile("cp.async.cg.shared.global [%0], [%1], 16;"
                                 :: "r"(d), "l"(s));
                }
            }
        }
        asm volatile("cp.async.commit_group;" ::: "memory");
    };

    // ---- prologue: B(0) via cp.async; A16(0) via direct LDG convert ----
    stageB(0);
    if (a_on) {
#pragma unroll
        for (int ks = 0; ks < 4; ks++) cvtA(0, ks, ldgA(0, ks));
    }
    asm volatile("cp.async.wait_group 0;" ::: "memory");
    __syncthreads();

    for (int kc = 0; kc < NKCH; kc++) {
        stageB(kc + 1);                          // B[(kc+1)&1]; MMA reads kc&1
        const bool more = (kc + 1 < NKCH) && a_on;
        const uint32_t Abuf = sbA16 + (kc & 1) * 16384;
        const uint32_t Bbuf = sbB + (kc & 1) * (NPACK * 128);

#pragma unroll
        for (int ks = 0; ks < 4; ks++) {
            // LDG next chunk's A piece early; STS after this ks' MMAs.
            float4 av;
            if (more) av = ldgA(kc + 1, ks);

            // ---- A fragments via ldmatrix.x4 ----
            uint32_t af[2][4];
#pragma unroll
            for (int mf = 0; mf < 2; mf++) {
                if (mf < nmf) {
                    uint32_t row = (uint32_t)(wm * 16 * nmf + mf * 16 + (lid & 15));
                    uint32_t off = row * 128 + (uint32_t)(ks * 32 + ((lid >> 4) & 1) * 16);
                    uint32_t addr = Abuf + (off ^ ((off >> 3) & 0x70));
                    asm volatile("ldmatrix.sync.aligned.m8n8.x4.shared.b16 {%0,%1,%2,%3}, [%4];"
                                 : "=r"(af[mf][0]), "=r"(af[mf][1]),
                                   "=r"(af[mf][2]), "=r"(af[mf][3]) : "r"(addr));
                }
            }
            // ---- B fragments: x4 per adjacent n-frag pair ----
#pragma unroll
            for (int np = 0; np < 5; np++) {
                const int nf = np * 2;
                int row = wn * 88 + (nf + ((lid >> 4) & 1)) * 8 + (lid & 7);
                uint32_t off = (uint32_t)(row * 128 + ks * 32 + ((lid >> 3) & 1) * 16);
                uint32_t addr = Bbuf + (off ^ ((off >> 3) & 0x70));
                uint32_t b0, b1, b2, b3;
                asm volatile("ldmatrix.sync.aligned.m8n8.x4.shared.b16 {%0,%1,%2,%3}, [%4];"
                             : "=r"(b0), "=r"(b1), "=r"(b2), "=r"(b3) : "r"(addr));
#pragma unroll
                for (int mf = 0; mf < 2; mf++) {
                    if (mf < nmf) {
                        asm volatile(
                            "mma.sync.aligned.m16n8k16.row.col.f32.f16.f16.f32 "
                            "{%0,%1,%2,%3},{%4,%5,%6,%7},{%8,%9},{%0,%1,%2,%3};"
                            : "+f"(acc[mf][nf][0]), "+f"(acc[mf][nf][1]),
                              "+f"(acc[mf][nf][2]), "+f"(acc[mf][nf][3])
                            : "r"(af[mf][0]), "r"(af[mf][1]), "r"(af[mf][2]), "r"(af[mf][3]),
                              "r"(b0), "r"(b1));
                        asm volatile(
                            "mma.sync.aligned.m16n8k16.row.col.f32.f16.f16.f32 "
                            "{%0,%1,%2,%3},{%4,%5,%6,%7},{%8,%9},{%0,%1,%2,%3};"
                            : "+f"(acc[mf][nf + 1][0]), "+f"(acc[mf][nf + 1][1]),
                              "+f"(acc[mf][nf + 1][2]), "+f"(acc[mf][nf + 1][3])
                            : "r"(af[mf][0]), "r"(af[mf][1]), "r"(af[mf][2]), "r"(af[mf][3]),
                              "r"(b2), "r"(b3));
                    }
                }
            }
            if (wn != 3) {   // ---- nf=10; wn==3 cols 344-351 = pad, skip ----
                const int nf = 10;
                int row = wn * 88 + nf * 8 + (lid & 7);
                uint32_t off = (uint32_t)(row * 128 + ks * 32 + ((lid >> 3) & 1) * 16);
                uint32_t addr = Bbuf + (off ^ ((off >> 3) & 0x70));
                uint32_t b0, b1;
                asm volatile("ldmatrix.sync.aligned.m8n8.x2.shared.b16 {%0,%1}, [%2];"
                             : "=r"(b0), "=r"(b1) : "r"(addr));
#pragma unroll
                for (int mf = 0; mf < 2; mf++) {
                    if (mf < nmf) {
                        asm volatile(
                            "mma.sync.aligned.m16n8k16.row.col.f32.f16.f16.f32 "
                            "{%0,%1,%2,%3},{%4,%5,%6,%7},{%8,%9},{%0,%1,%2,%3};"
                            : "+f"(acc[mf][nf][0]), "+f"(acc[mf][nf][1]),
                              "+f"(acc[mf][nf][2]), "+f"(acc[mf][nf][3])
                            : "r"(af[mf][0]), "r"(af[mf][1]), "r"(af[mf][2]), "r"(af[mf][3]),
                              "r"(b0), "r"(b1));
                    }
                }
            }
            if (more) cvtA(kc + 1, ks, av);   // STS into A16[(kc+1)&1]
        }

        asm volatile("cp.async.wait_group 0;" ::: "memory");  // B(kc+1) landed
        __syncthreads();   // publish A16(kc+1)+B(kc+1); fence buffer reuse
    }

    // =========================================================================
    // Epilogue: stage tile outputs in smem, then fully coalesced global writes.
    // Staging row r (word base r*STRIDE_W): [0..323] bbox, [324..404] scores.
    // =========================================================================
    // (final loop iteration's trailing __syncthreads already fenced all MMAs)

    // ---- zero the scores staging (masked class cols stay 0) ----
    for (int i = tid; i < arows * NSC; i += THREADS) {
        int r = i / NSC, c = i - r * NSC;
        s_stage[r * STRIDE_W + 324 + c] = 0.0f;
    }
    __syncthreads();

    // ---- scatter accumulators (+bias) into staging ----
#pragma unroll
    for (int mf = 0; mf < 2; mf++) {
        if (mf < nmf) {
#pragma unroll
            for (int half = 0; half < 2; half++) {
                const int r = wm * 16 * nmf + mf * 16 + q + half * 8;  // local row
                float* srow = s_stage + r * STRIDE_W;
#pragma unroll
                for (int nf = 0; nf < 11; nf++) {
#pragma unroll
                    for (int e = 0; e < 2; e++) {
                        const int c = wn * 88 + nf * 8 + t * 2 + e;
                        float vv = acc[mf][nf][half * 2 + e] + s_bias[c];
                        if (c == 0)        srow[324 + 0] = vv;
                        else if (c <= 12)  srow[324 + 1 + c_sel[c - 1]] = vv;
                        else if (c <= 336) srow[c - 13] = vv;
                    }
                }
            }
        }
    }
    __syncthreads();

    // ---- coalesced scores write: contiguous block [mbase*81, +arows*81) ----
    {
        float* dst = out + (size_t)mbase * NSC;
        for (int i = tid; i < arows * NSC; i += THREADS) {
            int r = i / NSC, c = i - r * NSC;
            dst[i] = s_stage[r * STRIDE_W + 324 + c];
        }
    }
    // ---- coalesced bbox write: float4, rows of 324 floats = 81 float4 ----
    {
        float4* dst = (float4*)(out + (size_t)N_TOK * NSC + (size_t)mbase * NBB);
        for (int j = tid; j < arows * 81; j += THREADS) {
            int r = j / 81, c4 = j - r * 81;
            dst[j] = *(const float4*)(s_stage + r * STRIDE_W + c4 * 4);
        }
    }
}

// ---------------------------------------------------------------------------
// Launch
// ---------------------------------------------------------------------------
extern "C" void kernel_launch(void* const* d_in, const int* in_sizes, int n_in,
                              void* d_out, int out_size) {
    const float* x      = (const float*)d_in[0];
    const float* W_cls  = (const float*)d_in[1];
    const float* b_cls  = (const float*)d_in[2];
    const float* W_sem  = (const float*)d_in[3];
    const float* b_sem  = (const float*)d_in[4];
    const float* W_bbox = (const float*)d_in[5];
    const float* b_bbox = (const float*)d_in[6];
    const float* sem_m  = (const float*)d_in[7];
    float* out = (float*)d_out;

    cudaFuncSetAttribute(fpn_gemm, cudaFuncAttributeMaxDynamicSharedMemorySize, SM_TOTAL);

    prep_kernel<<<SEM_BLKS + NPACK, 256>>>(W_cls, b_cls, W_sem, b_sem, W_bbox, b_bbox, sem_m);
    fpn_gemm<<<GRID, THREADS, SM_TOTAL>>>(x, out);
}

// round 15
// speedup vs baseline: 1.0257x; 1.0257x over previous
#include <cuda_runtime.h>
#include <cuda_fp16.h>
#include <stdint.h>

// ---------------------------------------------------------------------------
// Problem constants
// ---------------------------------------------------------------------------
#define N_TOK 65536
#define DIM   1024
#define S_SEM 200
#define NPACK 352      // 1 cls + 12 fused-sem + 324 bbox + 15 zero pad
#define NROWS_B 344    // B rows actually staged (344..351 pure pad, never read)
#define NSC   81
#define NBB   324
#define BK    64
#define NKCH  (DIM / BK)     // 16
#define THREADS 512
#define AROWF 68             // A32 smem row: 64 floats + 4 pad (272B)

// Heterogeneous tiling: 444 tiles of 128 rows (3 exact waves on 148 SMs),
// then 136 tiles of 64 rows (~0.5 wave at half duration).
#define NBIG   444
#define BIGROWS  (NBIG * 128)        // 56832
#define NSMALL 136                    // (65536-56832)/64
#define GRID   (NBIG + NSMALL)        // 580

// Packed fp16 weights + fp32 bias (built by prep kernel every launch)
__device__ __half g_Wp[NPACK * DIM];
__device__ float  g_bp[NPACK];

// Selected class indices (0-based into the 80 class cols): {i-1 : i in IGNORE2} U {79}
__constant__ int c_sel[12] = {1, 2, 16, 18, 29, 37, 47, 53, 63, 68, 72, 79};

__device__ __forceinline__ uint32_t smem_u32(const void* p) {
    uint32_t a;
    asm("{ .reg .u64 t; cvta.to.shared.u64 t, %1; cvt.u32.u64 %0, t; }"
        : "=r"(a) : "l"(p));
    return a;
}

// ---------------------------------------------------------------------------
// SMEM layout (bytes). GEMM region overlaid by epilogue staging (bias kept).
//   A32: single buffer  (128 x 272B = 34816)
//   A16: double buffer  (2 x 16384)
//   B  : TRIPLE buffer  (3 x 352 x 128B = 135168)
// ---------------------------------------------------------------------------
#define SMO_BIAS 0                                // 1536
#define SMO_A32  1536                             // 34816
#define SMO_A16  (SMO_A32 + 128 * AROWF * 4)      // 36352; 2 x 16384 = 32768
#define SMO_B    (SMO_A16 + 2 * 128 * 128)        // 69120; 3 x 45056 = 135168
#define SMO_STAGE 1536
#define STRIDE_W 412
#define SM_TOTAL (SMO_STAGE + 128 * STRIDE_W * 4) // 212480 (> 204288 gemm region)

// ---------------------------------------------------------------------------
// Prep: pack [W_cls ; sem_matrix[sel] @ W_sem / S ; W_bbox ; 0-pad] -> fp16
// ---------------------------------------------------------------------------
#define SEM_BLKS 48
__global__ void prep_kernel(const float* __restrict__ W_cls,
                            const float* __restrict__ b_cls,
                            const float* __restrict__ W_sem,
                            const float* __restrict__ b_sem,
                            const float* __restrict__ W_bbox,
                            const float* __restrict__ b_bbox,
                            const float* __restrict__ sem_m) {
    const int tid = threadIdx.x;
    const int bid = blockIdx.x;
    if (bid < SEM_BLKS) {
        __shared__ float sM[S_SEM];
        const int r = (bid >> 2) + 1;            // packed row 1..12
        const int chunk = bid & 3;
        const int sj = c_sel[r - 1];
        const float* M = sem_m + (size_t)sj * S_SEM;
        if (tid < S_SEM) sM[tid] = M[tid];
        __syncthreads();
        const int d = chunk * 256 + tid;
        const float* Wcol = W_sem + d;
        float a0 = 0.f, a1 = 0.f, a2 = 0.f, a3 = 0.f;
        float a4 = 0.f, a5 = 0.f, a6 = 0.f, a7 = 0.f;
#pragma unroll 5
        for (int s = 0; s < S_SEM; s += 8) {
            a0 += sM[s + 0] * __ldg(Wcol + (size_t)(s + 0) * DIM);
            a1 += sM[s + 1] * __ldg(Wcol + (size_t)(s + 1) * DIM);
            a2 += sM[s + 2] * __ldg(Wcol + (size_t)(s + 2) * DIM);
            a3 += sM[s + 3] * __ldg(Wcol + (size_t)(s + 3) * DIM);
            a4 += sM[s + 4] * __ldg(Wcol + (size_t)(s + 4) * DIM);
            a5 += sM[s + 5] * __ldg(Wcol + (size_t)(s + 5) * DIM);
            a6 += sM[s + 6] * __ldg(Wcol + (size_t)(s + 6) * DIM);
            a7 += sM[s + 7] * __ldg(Wcol + (size_t)(s + 7) * DIM);
        }
        float acc = ((a0 + a1) + (a2 + a3)) + ((a4 + a5) + (a6 + a7));
        g_Wp[(size_t)r * DIM + d] = __float2half(acc * (1.0f / S_SEM));
        if (chunk == 0 && tid < 32) {
            float p = 0.f;
            for (int s = tid; s < S_SEM; s += 32) p += sM[s] * b_sem[s];
#pragma unroll
            for (int o = 16; o > 0; o >>= 1) p += __shfl_xor_sync(0xffffffffu, p, o);
            if (tid == 0) g_bp[r] = p * (1.0f / S_SEM);
        }
    } else {
        const int r = bid - SEM_BLKS;            // 0..351
        if (r >= 1 && r <= 12) return;           // sem blocks own these
        __half* dst = g_Wp + (size_t)r * DIM;
        if (r == 0) {
            float4 v = ((const float4*)W_cls)[tid];
            ((__half2*)dst)[tid * 2 + 0] = __floats2half2_rn(v.x, v.y);
            ((__half2*)dst)[tid * 2 + 1] = __floats2half2_rn(v.z, v.w);
            if (tid == 0) g_bp[0] = b_cls[0];
        } else if (r < 13 + NBB) {
            const int c = r - 13;
            float4 v = ((const float4*)(W_bbox + (size_t)c * DIM))[tid];
            ((__half2*)dst)[tid * 2 + 0] = __floats2half2_rn(v.x, v.y);
            ((__half2*)dst)[tid * 2 + 1] = __floats2half2_rn(v.z, v.w);
            if (tid == 0) g_bp[r] = b_bbox[c];
        } else {
            ((__half2*)dst)[tid * 2 + 0] = __floats2half2_rn(0.f, 0.f);
            ((__half2*)dst)[tid * 2 + 1] = __floats2half2_rn(0.f, 0.f);
            if (tid == 0) g_bp[r] = 0.0f;
        }
    }
}

// ---------------------------------------------------------------------------
// Main GEMM. bid < NBIG: [128,1024]x[1024,352] tile; else [64,...] tail tile.
// 16 warps = 4M x 4N; warp tile (16*nmf) x 88; nmf = 2 (big) or 1 (small).
// ONE barrier per kc:
//   wait_group 0            (this thread's stage(kc) copies complete)
//   convert(kc)             (reads ONLY self-copied A32 -> A16[kc&1])
//   __syncthreads           (publish A16(kc) + B(kc); fences MMA(kc-1))
//   stage(kc+1)             (A32 single buf; B[(kc+1)%3])
//   MMA(kc)                 (reads A16[kc&1], B[kc%3])
// Hazards: B triple-buffered => stage(kc+1) target last read by MMA(kc-2),
// two barriers back. A16[kc&1] last read by MMA(kc-2), fenced by bar(kc-1).
// A32: reader convert(kc) pre-bar, writer stage(kc+1) post-bar.
// ---------------------------------------------------------------------------
__global__ void __launch_bounds__(THREADS, 1)
fpn_gemm(const float* __restrict__ x, float* __restrict__ out) {
    extern __shared__ char smem[];
    float* s_bias = (float*)(smem + SMO_BIAS);
    float* sA32 = (float*)(smem + SMO_A32);
    float* s_stage = (float*)(smem + SMO_STAGE);
    const uint32_t sbA32 = smem_u32(smem + SMO_A32);
    const uint32_t sbA16 = smem_u32(smem + SMO_A16);
    const uint32_t sbB   = smem_u32(smem + SMO_B);

    const int tid = threadIdx.x;
    const int wid = tid >> 5, lid = tid & 31;
    const int wm = wid >> 2, wn = wid & 3;        // 4 warps M x 4 warps N
    const int bid = blockIdx.x;
    const bool big = bid < NBIG;
    const int mbase = big ? bid * 128 : BIGROWS + (bid - NBIG) * 64;
    const int arows = big ? 128 : 64;             // tile rows
    const int nmf   = big ? 2 : 1;                // m-frags per warp
    const int q = lid >> 2, t = lid & 3;

    for (int i = tid; i < NPACK; i += THREADS) s_bias[i] = g_bp[i];

    float acc[2][11][4];
#pragma unroll
    for (int a = 0; a < 2; a++)
#pragma unroll
        for (int b = 0; b < 11; b++)
#pragma unroll
            for (int e = 0; e < 4; e++) acc[a][b][e] = 0.0f;

    // A ownership: thread owns row a_r = tid>>2, the 16 floats at cols
    // [a_j*16, a_j*16+16). Stage copies exactly these; convert reads them.
    const int a_r = tid >> 2;
    const int a_j = tid & 3;
    const bool a_on = a_r < arows;

    // --- stage chunk kc: A32 (self-mapped) + B[kc%3] via cp.async ---
    auto stage = [&](int kc) {
        if (kc < NKCH) {
            if (a_on) {
                const char* s = (const char*)(x + (size_t)(mbase + a_r) * DIM
                                              + kc * BK + a_j * 16);
                uint32_t d = sbA32 + a_r * (AROWF * 4) + a_j * 64;
#pragma unroll
                for (int u = 0; u < 4; u++)
                    asm volatile("cp.async.cg.shared.global [%0], [%1], 16;"
                                 :: "r"(d + u * 16), "l"(s + u * 16));
            }
            const char* ws = (const char*)g_Wp + (size_t)kc * (BK * 2);
            const uint32_t bdst = sbB + (kc % 3) * (NPACK * 128);
#pragma unroll
            for (int it = 0; it < 6; it++) {
                int i = it * THREADS + tid;          // 0..2751 (guarded)
                if (it < 5 || i < NROWS_B * 8) {
                    int r = i >> 3, j = i & 7;
                    uint32_t off = (uint32_t)(r * 128 + j * 16);
                    uint32_t d = bdst + (off ^ ((off >> 3) & 0x70));
                    const char* s = ws + (size_t)r * (DIM * 2) + j * 16;
                    asm volatile("cp.async.cg.shared.global [%0], [%1], 16;"
                                 :: "r"(d), "l"(s));
                }
            }
        }
        asm volatile("cp.async.commit_group;" ::: "memory");
    };

    stage(0);

    for (int kc = 0; kc < NKCH; kc++) {
        asm volatile("cp.async.wait_group 0;" ::: "memory");  // own copies done

        // ---- convert own A32 piece -> A16[kc&1] (SW128), self-sourced ----
        if (a_on) {
            const float* src = sA32 + a_r * AROWF + a_j * 16;
            float4 v0 = *(const float4*)(src + 0);
            float4 v1 = *(const float4*)(src + 4);
            float4 v2 = *(const float4*)(src + 8);
            float4 v3 = *(const float4*)(src + 12);
            uint4 w0, w1;
            union { __half2 h2; uint32_t u; } p;
            p.h2 = __floats2half2_rn(v0.x, v0.y); w0.x = p.u;
            p.h2 = __floats2half2_rn(v0.z, v0.w); w0.y = p.u;
            p.h2 = __floats2half2_rn(v1.x, v1.y); w0.z = p.u;
            p.h2 = __floats2half2_rn(v1.z, v1.w); w0.w = p.u;
            p.h2 = __floats2half2_rn(v2.x, v2.y); w1.x = p.u;
            p.h2 = __floats2half2_rn(v2.z, v2.w); w1.y = p.u;
            p.h2 = __floats2half2_rn(v3.x, v3.y); w1.z = p.u;
            p.h2 = __floats2half2_rn(v3.z, v3.w); w1.w = p.u;
            uint32_t o0 = (uint32_t)(a_r * 128 + a_j * 32);
            uint32_t o1 = o0 + 16;
            char* abuf = smem + SMO_A16 + (kc & 1) * 16384;
            *(uint4*)(abuf + (o0 ^ ((o0 >> 3) & 0x70))) = w0;
            *(uint4*)(abuf + (o1 ^ ((o1 >> 3) & 0x70))) = w1;
        }
        __syncthreads();   // publish A16(kc)+B(kc); fence MMA(kc-1) vs stage

        stage(kc + 1);     // A32 overwrite + B[(kc+1)%3]; overlap with MMA(kc)

        const uint32_t Abuf = sbA16 + (kc & 1) * 16384;
        const uint32_t Bbuf = sbB + (kc % 3) * (NPACK * 128);

#pragma unroll
        for (int ks = 0; ks < 4; ks++) {
            // ---- A fragments via ldmatrix.x4 ----
            uint32_t af[2][4];
#pragma unroll
            for (int mf = 0; mf < 2; mf++) {
                if (mf < nmf) {
                    uint32_t row = (uint32_t)(wm * 16 * nmf + mf * 16 + (lid & 15));
                    uint32_t off = row * 128 + (uint32_t)(ks * 32 + ((lid >> 4) & 1) * 16);
                    uint32_t addr = Abuf + (off ^ ((off >> 3) & 0x70));
                    asm volatile("ldmatrix.sync.aligned.m8n8.x4.shared.b16 {%0,%1,%2,%3}, [%4];"
                                 : "=r"(af[mf][0]), "=r"(af[mf][1]),
                                   "=r"(af[mf][2]), "=r"(af[mf][3]) : "r"(addr));
                }
            }
            // ---- B fragments: x4 per adjacent n-frag pair ----
#pragma unroll
            for (int np = 0; np < 5; np++) {
                const int nf = np * 2;
                int row = wn * 88 + (nf + ((lid >> 4) & 1)) * 8 + (lid & 7);
                uint32_t off = (uint32_t)(row * 128 + ks * 32 + ((lid >> 3) & 1) * 16);
                uint32_t addr = Bbuf + (off ^ ((off >> 3) & 0x70));
                uint32_t b0, b1, b2, b3;
                asm volatile("ldmatrix.sync.aligned.m8n8.x4.shared.b16 {%0,%1,%2,%3}, [%4];"
                             : "=r"(b0), "=r"(b1), "=r"(b2), "=r"(b3) : "r"(addr));
#pragma unroll
                for (int mf = 0; mf < 2; mf++) {
                    if (mf < nmf) {
                        asm volatile(
                            "mma.sync.aligned.m16n8k16.row.col.f32.f16.f16.f32 "
                            "{%0,%1,%2,%3},{%4,%5,%6,%7},{%8,%9},{%0,%1,%2,%3};"
                            : "+f"(acc[mf][nf][0]), "+f"(acc[mf][nf][1]),
                              "+f"(acc[mf][nf][2]), "+f"(acc[mf][nf][3])
                            : "r"(af[mf][0]), "r"(af[mf][1]), "r"(af[mf][2]), "r"(af[mf][3]),
                              "r"(b0), "r"(b1));
                        asm volatile(
                            "mma.sync.aligned.m16n8k16.row.col.f32.f16.f16.f32 "
                            "{%0,%1,%2,%3},{%4,%5,%6,%7},{%8,%9},{%0,%1,%2,%3};"
                            : "+f"(acc[mf][nf + 1][0]), "+f"(acc[mf][nf + 1][1]),
                              "+f"(acc[mf][nf + 1][2]), "+f"(acc[mf][nf + 1][3])
                            : "r"(af[mf][0]), "r"(af[mf][1]), "r"(af[mf][2]), "r"(af[mf][3]),
                              "r"(b2), "r"(b3));
                    }
                }
            }
            if (wn != 3) {   // ---- nf=10; wn==3 cols 344-351 = pad, skip ----
                const int nf = 10;
                int row = wn * 88 + nf * 8 + (lid & 7);
                uint32_t off = (uint32_t)(row * 128 + ks * 32 + ((lid >> 3) & 1) * 16);
                uint32_t addr = Bbuf + (off ^ ((off >> 3) & 0x70));
                uint32_t b0, b1;
                asm volatile("ldmatrix.sync.aligned.m8n8.x2.shared.b16 {%0,%1}, [%2];"
                             : "=r"(b0), "=r"(b1) : "r"(addr));
#pragma unroll
                for (int mf = 0; mf < 2; mf++) {
                    if (mf < nmf) {
                        asm volatile(
                            "mma.sync.aligned.m16n8k16.row.col.f32.f16.f16.f32 "
                            "{%0,%1,%2,%3},{%4,%5,%6,%7},{%8,%9},{%0,%1,%2,%3};"
                            : "+f"(acc[mf][nf][0]), "+f"(acc[mf][nf][1]),
                              "+f"(acc[mf][nf][2]), "+f"(acc[mf][nf][3])
                            : "r"(af[mf][0]), "r"(af[mf][1]), "r"(af[mf][2]), "r"(af[mf][3]),
                              "r"(b0), "r"(b1));
                    }
                }
            }
        }
    }

    // =========================================================================
    // Epilogue: stage tile outputs in smem, then fully coalesced global writes.
    // Staging row r (word base r*STRIDE_W): [0..323] bbox, [324..404] scores.
    // =========================================================================
    __syncthreads();          // all MMAs done; GEMM smem region reusable

    // ---- zero the scores staging (masked class cols stay 0) ----
    for (int i = tid; i < arows * NSC; i += THREADS) {
        int r = i / NSC, c = i - r * NSC;
        s_stage[r * STRIDE_W + 324 + c] = 0.0f;
    }
    __syncthreads();

    // ---- scatter accumulators (+bias) into staging ----
#pragma unroll
    for (int mf = 0; mf < 2; mf++) {
        if (mf < nmf) {
#pragma unroll
            for (int half = 0; half < 2; half++) {
                const int r = wm * 16 * nmf + mf * 16 + q + half * 8;  // local row
                float* srow = s_stage + r * STRIDE_W;
#pragma unroll
                for (int nf = 0; nf < 11; nf++) {
#pragma unroll
                    for (int e = 0; e < 2; e++) {
                        const int c = wn * 88 + nf * 8 + t * 2 + e;
                        float vv = acc[mf][nf][half * 2 + e] + s_bias[c];
                        if (c == 0)        srow[324 + 0] = vv;
                        else if (c <= 12)  srow[324 + 1 + c_sel[c - 1]] = vv;
                        else if (c <= 336) srow[c - 13] = vv;
                    }
                }
            }
        }
    }
    __syncthreads();

    // ---- coalesced scores write: contiguous block [mbase*81, +arows*81) ----
    {
        float* dst = out + (size_t)mbase * NSC;
        for (int i = tid; i < arows * NSC; i += THREADS) {
            int r = i / NSC, c = i - r * NSC;
            dst[i] = s_stage[r * STRIDE_W + 324 + c];
        }
    }
    // ---- coalesced bbox write: float4, rows of 324 floats = 81 float4 ----
    {
        float4* dst = (float4*)(out + (size_t)N_TOK * NSC + (size_t)mbase * NBB);
        for (int j = tid; j < arows * 81; j += THREADS) {
            int r = j / 81, c4 = j - r * 81;
            dst[j] = *(const float4*)(s_stage + r * STRIDE_W + c4 * 4);
        }
    }
}

// ---------------------------------------------------------------------------
// Launch
// ---------------------------------------------------------------------------
extern "C" void kernel_launch(void* const* d_in, const int* in_sizes, int n_in,
                              void* d_out, int out_size) {
    const float* x      = (const float*)d_in[0];
    const float* W_cls  = (const float*)d_in[1];
    const float* b_cls  = (const float*)d_in[2];
    const float* W_sem  = (const float*)d_in[3];
    const float* b_sem  = (const float*)d_in[4];
    const float* W_bbox = (const float*)d_in[5];
    const float* b_bbox = (const float*)d_in[6];
    const float* sem_m  = (const float*)d_in[7];
    float* out = (float*)d_out;

    cudaFuncSetAttribute(fpn_gemm, cudaFuncAttributeMaxDynamicSharedMemorySize, SM_TOTAL);

    prep_kernel<<<SEM_BLKS + NPACK, 256>>>(W_cls, b_cls, W_sem, b_sem, W_bbox, b_bbox, sem_m);
    fpn_gemm<<<GRID, THREADS, SM_TOTAL>>>(x, out);
}

// round 16
// speedup vs baseline: 1.1021x; 1.0745x over previous
#include <cuda_runtime.h>
#include <cuda_fp16.h>
#include <stdint.h>

// ---------------------------------------------------------------------------
// Problem constants
// ---------------------------------------------------------------------------
#define N_TOK 65536
#define DIM   1024
#define S_SEM 200
#define NPACK 352      // 1 cls + 12 fused-sem + 324 bbox + 15 zero pad
#define NROWS_B 344    // B rows actually staged (344..351 pure pad, never read)
#define NSC   81
#define NBB   324
#define BK    64
#define NKCH  (DIM / BK)     // 16
#define THREADS 512
#define AROWF 68             // A32 smem row: 64 floats + 4 pad

// Heterogeneous tiling: 444 tiles of 128 rows (3 exact waves on 148 SMs),
// then 136 tiles of 64 rows (~0.5 wave at half duration).
#define NBIG   444
#define BIGROWS  (NBIG * 128)        // 56832
#define NSMALL 136                    // (65536-56832)/64
#define GRID   (NBIG + NSMALL)        // 580

// Packed fp16 weights + fp32 bias (built by prep kernel every launch)
__device__ __half g_Wp[NPACK * DIM];
__device__ float  g_bp[NPACK];

// Selected class indices (0-based into the 80 class cols): {i-1 : i in IGNORE2} U {79}
__constant__ int c_sel[12] = {1, 2, 16, 18, 29, 37, 47, 53, 63, 68, 72, 79};

__device__ __forceinline__ uint32_t smem_u32(const void* p) {
    uint32_t a;
    asm("{ .reg .u64 t; cvta.to.shared.u64 t, %1; cvt.u32.u64 %0, t; }"
        : "=r"(a) : "l"(p));
    return a;
}

// ---------------------------------------------------------------------------
// SMEM layout (bytes). GEMM region overlaid by epilogue staging (bias kept).
//   A32: DOUBLE buffer (2 x 128 x 272B = 69632)
//   A16: single buffer (16384)
//   B  : double buffer (2 x 352 x 128B = 90112)
// ---------------------------------------------------------------------------
#define SMO_BIAS 0                                // 1536
#define SMO_A32  1536                             // 2 x 34816 = 69632
#define SMO_A16  (SMO_A32 + 2 * 128 * AROWF * 4)  // 71168; 16384
#define SMO_B    (SMO_A16 + 128 * 128)            // 87552; 2 x 45056 = 90112
#define SMO_STAGE 1536
#define STRIDE_W 412
#define SM_TOTAL (SMO_STAGE + 128 * STRIDE_W * 4) // 212480 (> 177664 gemm region)

// ---------------------------------------------------------------------------
// Prep: pack [W_cls ; sem_matrix[sel] @ W_sem / S ; W_bbox ; 0-pad] -> fp16
// ---------------------------------------------------------------------------
#define SEM_BLKS 48
__global__ void prep_kernel(const float* __restrict__ W_cls,
                            const float* __restrict__ b_cls,
                            const float* __restrict__ W_sem,
                            const float* __restrict__ b_sem,
                            const float* __restrict__ W_bbox,
                            const float* __restrict__ b_bbox,
                            const float* __restrict__ sem_m) {
    const int tid = threadIdx.x;
    const int bid = blockIdx.x;
    if (bid < SEM_BLKS) {
        __shared__ float sM[S_SEM];
        const int r = (bid >> 2) + 1;            // packed row 1..12
        const int chunk = bid & 3;
        const int sj = c_sel[r - 1];
        const float* M = sem_m + (size_t)sj * S_SEM;
        if (tid < S_SEM) sM[tid] = M[tid];
        __syncthreads();
        const int d = chunk * 256 + tid;
        const float* Wcol = W_sem + d;
        float a0 = 0.f, a1 = 0.f, a2 = 0.f, a3 = 0.f;
        float a4 = 0.f, a5 = 0.f, a6 = 0.f, a7 = 0.f;
#pragma unroll 5
        for (int s = 0; s < S_SEM; s += 8) {
            a0 += sM[s + 0] * __ldg(Wcol + (size_t)(s + 0) * DIM);
            a1 += sM[s + 1] * __ldg(Wcol + (size_t)(s + 1) * DIM);
            a2 += sM[s + 2] * __ldg(Wcol + (size_t)(s + 2) * DIM);
            a3 += sM[s + 3] * __ldg(Wcol + (size_t)(s + 3) * DIM);
            a4 += sM[s + 4] * __ldg(Wcol + (size_t)(s + 4) * DIM);
            a5 += sM[s + 5] * __ldg(Wcol + (size_t)(s + 5) * DIM);
            a6 += sM[s + 6] * __ldg(Wcol + (size_t)(s + 6) * DIM);
            a7 += sM[s + 7] * __ldg(Wcol + (size_t)(s + 7) * DIM);
        }
        float acc = ((a0 + a1) + (a2 + a3)) + ((a4 + a5) + (a6 + a7));
        g_Wp[(size_t)r * DIM + d] = __float2half(acc * (1.0f / S_SEM));
        if (chunk == 0 && tid < 32) {
            float p = 0.f;
            for (int s = tid; s < S_SEM; s += 32) p += sM[s] * b_sem[s];
#pragma unroll
            for (int o = 16; o > 0; o >>= 1) p += __shfl_xor_sync(0xffffffffu, p, o);
            if (tid == 0) g_bp[r] = p * (1.0f / S_SEM);
        }
    } else {
        const int r = bid - SEM_BLKS;            // 0..351
        if (r >= 1 && r <= 12) return;           // sem blocks own these
        __half* dst = g_Wp + (size_t)r * DIM;
        if (r == 0) {
            float4 v = ((const float4*)W_cls)[tid];
            ((__half2*)dst)[tid * 2 + 0] = __floats2half2_rn(v.x, v.y);
            ((__half2*)dst)[tid * 2 + 1] = __floats2half2_rn(v.z, v.w);
            if (tid == 0) g_bp[0] = b_cls[0];
        } else if (r < 13 + NBB) {
            const int c = r - 13;
            float4 v = ((const float4*)(W_bbox + (size_t)c * DIM))[tid];
            ((__half2*)dst)[tid * 2 + 0] = __floats2half2_rn(v.x, v.y);
            ((__half2*)dst)[tid * 2 + 1] = __floats2half2_rn(v.z, v.w);
            if (tid == 0) g_bp[r] = b_bbox[c];
        } else {
            ((__half2*)dst)[tid * 2 + 0] = __floats2half2_rn(0.f, 0.f);
            ((__half2*)dst)[tid * 2 + 1] = __floats2half2_rn(0.f, 0.f);
            if (tid == 0) g_bp[r] = 0.0f;
        }
    }
}

// ---------------------------------------------------------------------------
// Main GEMM. bid < NBIG: [128,1024]x[1024,352] tile; else [64,...] tail tile.
// 16 warps = 4M x 4N; warp tile (16*nmf) x 88; nmf = 2 (big) or 1 (small).
// Schedule per kc (R12 structure, stage moved up one slot):
//   wait_group 0            (stage(kc) landed)
//   __syncthreads  [bar1]   (publish A32(kc)/B(kc); fences MMA(kc-1))
//   stage(kc+1)             (A32[(kc+1)&1], B[(kc+1)&1]: prev reader fenced)
//   convert(kc)             (A32[kc&1] -> A16, single buf: MMA(kc-1) fenced)
//   __syncthreads  [bar2]   (publish A16)
//   MMA(kc)                 (reads A16, B[kc&1])
// ---------------------------------------------------------------------------
__global__ void __launch_bounds__(THREADS, 1)
fpn_gemm(const float* __restrict__ x, float* __restrict__ out) {
    extern __shared__ char smem[];
    float* s_bias = (float*)(smem + SMO_BIAS);
    float* sA32 = (float*)(smem + SMO_A32);
    float* s_stage = (float*)(smem + SMO_STAGE);
    const uint32_t sbA32 = smem_u32(smem + SMO_A32);
    const uint32_t sbA16 = smem_u32(smem + SMO_A16);
    const uint32_t sbB   = smem_u32(smem + SMO_B);

    const int tid = threadIdx.x;
    const int wid = tid >> 5, lid = tid & 31;
    const int wm = wid >> 2, wn = wid & 3;        // 4 warps M x 4 warps N
    const int bid = blockIdx.x;
    const bool big = bid < NBIG;
    const int mbase = big ? bid * 128 : BIGROWS + (bid - NBIG) * 64;
    const int arows = big ? 128 : 64;             // tile rows
    const int nmf   = big ? 2 : 1;                // m-frags per warp
    const int q = lid >> 2, t = lid & 3;

    for (int i = tid; i < NPACK; i += THREADS) s_bias[i] = g_bp[i];

    float acc[2][11][4];
#pragma unroll
    for (int a = 0; a < 2; a++)
#pragma unroll
        for (int b = 0; b < 11; b++)
#pragma unroll
            for (int e = 0; e < 4; e++) acc[a][b][e] = 0.0f;

    // --- stage chunk kc: A32[kc&1] + B[kc&1] via cp.async (R12 mapping) ---
    auto stage = [&](int kc) {
        if (kc < NKCH) {
            const char* xs = (const char*)(x + (size_t)mbase * DIM + kc * BK);
            const uint32_t adst = sbA32 + (kc & 1) * (128 * AROWF * 4);
#pragma unroll
            for (int it = 0; it < 4; it++) {
                int i = it * THREADS + tid;          // 0..2047
                int r = i >> 4, j = i & 15;
                if (r < arows) {
                    uint32_t d = adst + r * (AROWF * 4) + j * 16;
                    const char* s = xs + (size_t)r * (DIM * 4) + j * 16;
                    asm volatile("cp.async.cg.shared.global [%0], [%1], 16;"
                                 :: "r"(d), "l"(s));
                }
            }
            const char* ws = (const char*)g_Wp + (size_t)kc * (BK * 2);
            const uint32_t bdst = sbB + (kc & 1) * (NPACK * 128);
#pragma unroll
            for (int it = 0; it < 6; it++) {
                int i = it * THREADS + tid;          // 0..3071 (guarded)
                if (it < 5 || i < NROWS_B * 8) {
                    int r = i >> 3, j = i & 7;
                    uint32_t off = (uint32_t)(r * 128 + j * 16);
                    uint32_t d = bdst + (off ^ ((off >> 3) & 0x70));
                    const char* s = ws + (size_t)r * (DIM * 2) + j * 16;
                    asm volatile("cp.async.cg.shared.global [%0], [%1], 16;"
                                 :: "r"(d), "l"(s));
                }
            }
        }
        asm volatile("cp.async.commit_group;" ::: "memory");
    };

    stage(0);

    for (int kc = 0; kc < NKCH; kc++) {
        asm volatile("cp.async.wait_group 0;" ::: "memory");  // stage(kc) landed
        __syncthreads();   // bar1: publish A32(kc)/B(kc); fence MMA(kc-1)

        stage(kc + 1);     // early: lands across convert + bar2 + MMA(kc)

        // ---- convert A32[kc&1] -> A16 (SW128): 4 threads/row, 16 f32 each ----
        {
            const int r = tid >> 2, j = tid & 3;          // 128 rows x 4
            if (r < arows) {
                const float* src = sA32 + (kc & 1) * (128 * AROWF) + r * AROWF + j * 16;
                float4 v0 = *(const float4*)(src + 0);
                float4 v1 = *(const float4*)(src + 4);
                float4 v2 = *(const float4*)(src + 8);
                float4 v3 = *(const float4*)(src + 12);
                uint4 w0, w1;
                union { __half2 h2; uint32_t u; } p;
                p.h2 = __floats2half2_rn(v0.x, v0.y); w0.x = p.u;
                p.h2 = __floats2half2_rn(v0.z, v0.w); w0.y = p.u;
                p.h2 = __floats2half2_rn(v1.x, v1.y); w0.z = p.u;
                p.h2 = __floats2half2_rn(v1.z, v1.w); w0.w = p.u;
                p.h2 = __floats2half2_rn(v2.x, v2.y); w1.x = p.u;
                p.h2 = __floats2half2_rn(v2.z, v2.w); w1.y = p.u;
                p.h2 = __floats2half2_rn(v3.x, v3.y); w1.z = p.u;
                p.h2 = __floats2half2_rn(v3.z, v3.w); w1.w = p.u;
                uint32_t o0 = (uint32_t)(r * 128 + j * 32);
                uint32_t o1 = o0 + 16;
                *(uint4*)(smem + SMO_A16 + (o0 ^ ((o0 >> 3) & 0x70))) = w0;
                *(uint4*)(smem + SMO_A16 + (o1 ^ ((o1 >> 3) & 0x70))) = w1;
            }
        }
        __syncthreads();   // bar2: A16 ready

        const uint32_t Bbuf = sbB + (kc & 1) * (NPACK * 128);

#pragma unroll
        for (int ks = 0; ks < 4; ks++) {
            // ---- A fragments via ldmatrix.x4 ----
            uint32_t af[2][4];
#pragma unroll
            for (int mf = 0; mf < 2; mf++) {
                if (mf < nmf) {
                    uint32_t row = (uint32_t)(wm * 16 * nmf + mf * 16 + (lid & 15));
                    uint32_t off = row * 128 + (uint32_t)(ks * 32 + ((lid >> 4) & 1) * 16);
                    uint32_t addr = sbA16 + (off ^ ((off >> 3) & 0x70));
                    asm volatile("ldmatrix.sync.aligned.m8n8.x4.shared.b16 {%0,%1,%2,%3}, [%4];"
                                 : "=r"(af[mf][0]), "=r"(af[mf][1]),
                                   "=r"(af[mf][2]), "=r"(af[mf][3]) : "r"(addr));
                }
            }
            // ---- B fragments: x4 per adjacent n-frag pair ----
#pragma unroll
            for (int np = 0; np < 5; np++) {
                const int nf = np * 2;
                int row = wn * 88 + (nf + ((lid >> 4) & 1)) * 8 + (lid & 7);
                uint32_t off = (uint32_t)(row * 128 + ks * 32 + ((lid >> 3) & 1) * 16);
                uint32_t addr = Bbuf + (off ^ ((off >> 3) & 0x70));
                uint32_t b0, b1, b2, b3;
                asm volatile("ldmatrix.sync.aligned.m8n8.x4.shared.b16 {%0,%1,%2,%3}, [%4];"
                             : "=r"(b0), "=r"(b1), "=r"(b2), "=r"(b3) : "r"(addr));
#pragma unroll
                for (int mf = 0; mf < 2; mf++) {
                    if (mf < nmf) {
                        asm volatile(
                            "mma.sync.aligned.m16n8k16.row.col.f32.f16.f16.f32 "
                            "{%0,%1,%2,%3},{%4,%5,%6,%7},{%8,%9},{%0,%1,%2,%3};"
                            : "+f"(acc[mf][nf][0]), "+f"(acc[mf][nf][1]),
                              "+f"(acc[mf][nf][2]), "+f"(acc[mf][nf][3])
                            : "r"(af[mf][0]), "r"(af[mf][1]), "r"(af[mf][2]), "r"(af[mf][3]),
                              "r"(b0), "r"(b1));
                        asm volatile(
                            "mma.sync.aligned.m16n8k16.row.col.f32.f16.f16.f32 "
                            "{%0,%1,%2,%3},{%4,%5,%6,%7},{%8,%9},{%0,%1,%2,%3};"
                            : "+f"(acc[mf][nf + 1][0]), "+f"(acc[mf][nf + 1][1]),
                              "+f"(acc[mf][nf + 1][2]), "+f"(acc[mf][nf + 1][3])
                            : "r"(af[mf][0]), "r"(af[mf][1]), "r"(af[mf][2]), "r"(af[mf][3]),
                              "r"(b2), "r"(b3));
                    }
                }
            }
            if (wn != 3) {   // ---- nf=10; wn==3 cols 344-351 = pad, skip ----
                const int nf = 10;
                int row = wn * 88 + nf * 8 + (lid & 7);
                uint32_t off = (uint32_t)(row * 128 + ks * 32 + ((lid >> 3) & 1) * 16);
                uint32_t addr = Bbuf + (off ^ ((off >> 3) & 0x70));
                uint32_t b0, b1;
                asm volatile("ldmatrix.sync.aligned.m8n8.x2.shared.b16 {%0,%1}, [%2];"
                             : "=r"(b0), "=r"(b1) : "r"(addr));
#pragma unroll
                for (int mf = 0; mf < 2; mf++) {
                    if (mf < nmf) {
                        asm volatile(
                            "mma.sync.aligned.m16n8k16.row.col.f32.f16.f16.f32 "
                            "{%0,%1,%2,%3},{%4,%5,%6,%7},{%8,%9},{%0,%1,%2,%3};"
                            : "+f"(acc[mf][nf][0]), "+f"(acc[mf][nf][1]),
                              "+f"(acc[mf][nf][2]), "+f"(acc[mf][nf][3])
                            : "r"(af[mf][0]), "r"(af[mf][1]), "r"(af[mf][2]), "r"(af[mf][3]),
                              "r"(b0), "r"(b1));
                    }
                }
            }
        }
    }

    // =========================================================================
    // Epilogue: stage tile outputs in smem, then fully coalesced global writes.
    // Staging row r (word base r*STRIDE_W): [0..323] bbox, [324..404] scores.
    // =========================================================================
    __syncthreads();          // all MMAs done; GEMM smem region reusable

    // ---- zero the scores staging (masked class cols stay 0) ----
    for (int i = tid; i < arows * NSC; i += THREADS) {
        int r = i / NSC, c = i - r * NSC;
        s_stage[r * STRIDE_W + 324 + c] = 0.0f;
    }
    __syncthreads();

    // ---- scatter accumulators (+bias) into staging ----
#pragma unroll
    for (int mf = 0; mf < 2; mf++) {
        if (mf < nmf) {
#pragma unroll
            for (int half = 0; half < 2; half++) {
                const int r = wm * 16 * nmf + mf * 16 + q + half * 8;  // local row
                float* srow = s_stage + r * STRIDE_W;
#pragma unroll
                for (int nf = 0; nf < 11; nf++) {
#pragma unroll
                    for (int e = 0; e < 2; e++) {
                        const int c = wn * 88 + nf * 8 + t * 2 + e;
                        float vv = acc[mf][nf][half * 2 + e] + s_bias[c];
                        if (c == 0)        srow[324 + 0] = vv;
                        else if (c <= 12)  srow[324 + 1 + c_sel[c - 1]] = vv;
                        else if (c <= 336) srow[c - 13] = vv;
                    }
                }
            }
        }
    }
    __syncthreads();

    // ---- coalesced scores write: contiguous block [mbase*81, +arows*81) ----
    {
        float* dst = out + (size_t)mbase * NSC;
        for (int i = tid; i < arows * NSC; i += THREADS) {
            int r = i / NSC, c = i - r * NSC;
            dst[i] = s_stage[r * STRIDE_W + 324 + c];
        }
    }
    // ---- coalesced bbox write: float4, rows of 324 floats = 81 float4 ----
    {
        float4* dst = (float4*)(out + (size_t)N_TOK * NSC + (size_t)mbase * NBB);
        for (int j = tid; j < arows * 81; j += THREADS) {
            int r = j / 81, c4 = j - r * 81;
            dst[j] = *(const float4*)(s_stage + r * STRIDE_W + c4 * 4);
        }
    }
}

// ---------------------------------------------------------------------------
// Launch
// ---------------------------------------------------------------------------
extern "C" void kernel_launch(void* const* d_in, const int* in_sizes, int n_in,
                              void* d_out, int out_size) {
    const float* x      = (const float*)d_in[0];
    const float* W_cls  = (const float*)d_in[1];
    const float* b_cls  = (const float*)d_in[2];
    const float* W_sem  = (const float*)d_in[3];
    const float* b_sem  = (const float*)d_in[4];
    const float* W_bbox = (const float*)d_in[5];
    const float* b_bbox = (const float*)d_in[6];
    const float* sem_m  = (const float*)d_in[7];
    float* out = (float*)d_out;

    cudaFuncSetAttribute(fpn_gemm, cudaFuncAttributeMaxDynamicSharedMemorySize, SM_TOTAL);

    prep_kernel<<<SEM_BLKS + NPACK, 256>>>(W_cls, b_cls, W_sem, b_sem, W_bbox, b_bbox, sem_m);
    fpn_gemm<<<GRID, THREADS, SM_TOTAL>>>(x, out);
}

// round 17
// speedup vs baseline: 1.1671x; 1.0590x over previous
#include <cuda_runtime.h>
#include <cuda_fp16.h>
#include <stdint.h>

// ---------------------------------------------------------------------------
// Problem constants
// ---------------------------------------------------------------------------
#define N_TOK 65536
#define DIM   1024
#define S_SEM 200
#define NPACK 352      // 1 cls + 12 fused-sem + 324 bbox + 15 zero pad
#define NROWS_B 344    // B rows actually staged (344..351 pure pad, never read)
#define NSC   81
#define NBB   324
#define BK    64
#define NKCH  (DIM / BK)     // 16
#define THREADS 512
#define AROWF 68             // A32 smem row: 64 floats + 4 pad

// Heterogeneous tiling: 444 tiles of 128 rows (3 exact waves on 148 SMs),
// then 136 tiles of 64 rows (~0.5 wave at half duration).
#define NBIG   444
#define BIGROWS  (NBIG * 128)        // 56832
#define NSMALL 136                    // (65536-56832)/64
#define GRID   (NBIG + NSMALL)        // 580

// Packed fp16 weights + fp32 bias (built by prep kernel every launch)
__device__ __half g_Wp[NPACK * DIM];
__device__ float  g_bp[NPACK];

// Selected class indices (0-based into the 80 class cols): {i-1 : i in IGNORE2} U {79}
__constant__ int c_sel[12] = {1, 2, 16, 18, 29, 37, 47, 53, 63, 68, 72, 79};

__device__ __forceinline__ uint32_t smem_u32(const void* p) {
    uint32_t a;
    asm("{ .reg .u64 t; cvta.to.shared.u64 t, %1; cvt.u32.u64 %0, t; }"
        : "=r"(a) : "l"(p));
    return a;
}

// ---------------------------------------------------------------------------
// SMEM layout (bytes). GEMM region (A32/A16/B) overlaid by epilogue staging.
// Staging: 128 rows x 412 words; row: [0..323] bbox, [324..404] scores.
// ---------------------------------------------------------------------------
#define SMO_BIAS 0                                // 1536
#define SMO_A32  1536                             // 128 x 272B = 34816 (single buf)
#define SMO_A16  (SMO_A32 + 128 * AROWF * 4)      // 36352; 128 x 128B = 16384
#define SMO_B    (SMO_A16 + 128 * 128)            // 52736; 2 x 352 x 128B = 90112
#define SMO_STAGE 1536
#define STRIDE_W 412
#define SM_TOTAL (SMO_STAGE + 128 * STRIDE_W * 4) // 212480

// ---------------------------------------------------------------------------
// Prep: pack [W_cls ; sem_matrix[sel] @ W_sem / S ; W_bbox ; 0-pad] -> fp16.
// Sem fusion: 192 blocks (12 rows x 16 chunks of 64 cols), 256 thr =
// 64 cols x 4 s-groups of 50; smem-reduced. Copies: 340 blocks.
// ---------------------------------------------------------------------------
#define SEMB 192
#define PREP_GRID (SEMB + 340)
__global__ void prep_kernel(const float* __restrict__ W_cls,
                            const float* __restrict__ b_cls,
                            const float* __restrict__ W_sem,
                            const float* __restrict__ b_sem,
                            const float* __restrict__ W_bbox,
                            const float* __restrict__ b_bbox,
                            const float* __restrict__ sem_m) {
    const int tid = threadIdx.x;
    const int bid = blockIdx.x;
    if (bid < SEMB) {
        __shared__ float sM[S_SEM];
        __shared__ float part[256];
        const int r = (bid >> 4) + 1;            // packed row 1..12
        const int chunk = bid & 15;              // 64-col chunk
        const int sj = c_sel[r - 1];
        if (tid < S_SEM) sM[tid] = sem_m[(size_t)sj * S_SEM + tid];
        __syncthreads();
        const int dl = tid & 63, sg = tid >> 6;  // col-local, s-group
        const int d = chunk * 64 + dl;
        const float* Wcol = W_sem + d;
        const int s0 = sg * 50;
        float a0 = 0.f, a1 = 0.f;
#pragma unroll 5
        for (int s = 0; s < 50; s += 2) {
            a0 += sM[s0 + s]     * __ldg(Wcol + (size_t)(s0 + s) * DIM);
            a1 += sM[s0 + s + 1] * __ldg(Wcol + (size_t)(s0 + s + 1) * DIM);
        }
        part[tid] = a0 + a1;
        __syncthreads();
        if (sg == 0) {
            float v = part[dl] + part[64 + dl] + part[128 + dl] + part[192 + dl];
            g_Wp[(size_t)r * DIM + d] = __float2half(v * (1.0f / S_SEM));
        }
        if (chunk == 0 && tid < 32) {
            float p = 0.f;
            for (int s = tid; s < S_SEM; s += 32) p += sM[s] * b_sem[s];
#pragma unroll
            for (int o = 16; o > 0; o >>= 1) p += __shfl_xor_sync(0xffffffffu, p, o);
            if (tid == 0) g_bp[r] = p * (1.0f / S_SEM);
        }
    } else {
        const int r2 = bid - SEMB;               // 0..339
        const int r = (r2 == 0) ? 0 : (r2 + 12); // 0, then 13..351
        __half* dst = g_Wp + (size_t)r * DIM;
        if (r == 0) {
            float4 v = ((const float4*)W_cls)[tid];
            ((__half2*)dst)[tid * 2 + 0] = __floats2half2_rn(v.x, v.y);
            ((__half2*)dst)[tid * 2 + 1] = __floats2half2_rn(v.z, v.w);
            if (tid == 0) g_bp[0] = b_cls[0];
        } else if (r < 13 + NBB) {
            const int c = r - 13;
            float4 v = ((const float4*)(W_bbox + (size_t)c * DIM))[tid];
            ((__half2*)dst)[tid * 2 + 0] = __floats2half2_rn(v.x, v.y);
            ((__half2*)dst)[tid * 2 + 1] = __floats2half2_rn(v.z, v.w);
            if (tid == 0) g_bp[r] = b_bbox[c];
        } else {
            ((__half2*)dst)[tid * 2 + 0] = __floats2half2_rn(0.f, 0.f);
            ((__half2*)dst)[tid * 2 + 1] = __floats2half2_rn(0.f, 0.f);
            if (tid == 0) g_bp[r] = 0.0f;
        }
    }
}

// ---------------------------------------------------------------------------
// Main GEMM (R12 champion, verbatim; only B staging trimmed to NROWS_B).
// bid < NBIG: [128,1024]x[1024,352] tile; else [64,...] tail tile.
// 16 warps = 4M x 4N; warp tile (16*nmf) x 88; nmf = 2 (big) or 1 (small).
// Schedule per kc:
//   wait_group 0 -> bar -> convert(A32->A16) -> bar -> stage(kc+1) -> MMA(kc)
// ---------------------------------------------------------------------------
__global__ void __launch_bounds__(THREADS, 1)
fpn_gemm(const float* __restrict__ x, float* __restrict__ out) {
    extern __shared__ char smem[];
    float* s_bias = (float*)(smem + SMO_BIAS);
    float* sA32 = (float*)(smem + SMO_A32);
    float* s_stage = (float*)(smem + SMO_STAGE);
    const uint32_t sbA32 = smem_u32(smem + SMO_A32);
    const uint32_t sbA16 = smem_u32(smem + SMO_A16);
    const uint32_t sbB   = smem_u32(smem + SMO_B);

    const int tid = threadIdx.x;
    const int wid = tid >> 5, lid = tid & 31;
    const int wm = wid >> 2, wn = wid & 3;        // 4 warps M x 4 warps N
    const int bid = blockIdx.x;
    const bool big = bid < NBIG;
    const int mbase = big ? bid * 128 : BIGROWS + (bid - NBIG) * 64;
    const int arows = big ? 128 : 64;             // tile rows
    const int nmf   = big ? 2 : 1;                // m-frags per warp
    const int q = lid >> 2, t = lid & 3;

    for (int i = tid; i < NPACK; i += THREADS) s_bias[i] = g_bp[i];

    float acc[2][11][4];
#pragma unroll
    for (int a = 0; a < 2; a++)
#pragma unroll
        for (int b = 0; b < 11; b++)
#pragma unroll
            for (int e = 0; e < 4; e++) acc[a][b][e] = 0.0f;

    // --- stage chunk kc: A32 (single buf, arows rows) + B (double buf) ---
    auto stage = [&](int kc) {
        if (kc < NKCH) {
            const char* xs = (const char*)(x + (size_t)mbase * DIM + kc * BK);
#pragma unroll
            for (int it = 0; it < 4; it++) {
                int i = it * THREADS + tid;          // 0..2047
                int r = i >> 4, j = i & 15;
                if (r < arows) {
                    uint32_t d = sbA32 + r * (AROWF * 4) + j * 16;
                    const char* s = xs + (size_t)r * (DIM * 4) + j * 16;
                    asm volatile("cp.async.cg.shared.global [%0], [%1], 16;"
                                 :: "r"(d), "l"(s));
                }
            }
            const char* ws = (const char*)g_Wp + (size_t)kc * (BK * 2);
            const uint32_t bdst = sbB + (kc & 1) * (NPACK * 128);
#pragma unroll
            for (int it = 0; it < 6; it++) {
                int i = it * THREADS + tid;          // guarded to NROWS_B*8
                if (it < 5 || i < NROWS_B * 8) {
                    int r = i >> 3, j = i & 7;
                    uint32_t off = (uint32_t)(r * 128 + j * 16);
                    uint32_t d = bdst + (off ^ ((off >> 3) & 0x70));
                    const char* s = ws + (size_t)r * (DIM * 2) + j * 16;
                    asm volatile("cp.async.cg.shared.global [%0], [%1], 16;"
                                 :: "r"(d), "l"(s));
                }
            }
        }
        asm volatile("cp.async.commit_group;" ::: "memory");
    };

    stage(0);

    for (int kc = 0; kc < NKCH; kc++) {
        asm volatile("cp.async.wait_group 0;" ::: "memory");  // stage(kc) landed
        __syncthreads();   // all warps past MMA(kc-1); A32/B(kc) visible

        // ---- convert A32 -> A16 (SW128): 4 threads/row, 16 f32 each ----
        {
            const int r = tid >> 2, j = tid & 3;          // 128 rows x 4
            if (r < arows) {
                const float* src = sA32 + r * AROWF + j * 16;
                float4 v0 = *(const float4*)(src + 0);
                float4 v1 = *(const float4*)(src + 4);
                float4 v2 = *(const float4*)(src + 8);
                float4 v3 = *(const float4*)(src + 12);
                uint4 w0, w1;
                union { __half2 h2; uint32_t u; } p;
                p.h2 = __floats2half2_rn(v0.x, v0.y); w0.x = p.u;
                p.h2 = __floats2half2_rn(v0.z, v0.w); w0.y = p.u;
                p.h2 = __floats2half2_rn(v1.x, v1.y); w0.z = p.u;
                p.h2 = __floats2half2_rn(v1.z, v1.w); w0.w = p.u;
                p.h2 = __floats2half2_rn(v2.x, v2.y); w1.x = p.u;
                p.h2 = __floats2half2_rn(v2.z, v2.w); w1.y = p.u;
                p.h2 = __floats2half2_rn(v3.x, v3.y); w1.z = p.u;
                p.h2 = __floats2half2_rn(v3.z, v3.w); w1.w = p.u;
                uint32_t o0 = (uint32_t)(r * 128 + j * 32);
                uint32_t o1 = o0 + 16;
                *(uint4*)(smem + SMO_A16 + (o0 ^ ((o0 >> 3) & 0x70))) = w0;
                *(uint4*)(smem + SMO_A16 + (o1 ^ ((o1 >> 3) & 0x70))) = w1;
            }
        }
        __syncthreads();   // A16 ready; A32 + B((kc+1)&1) safe to overwrite

        stage(kc + 1);     // overlap next loads with MMA(kc)

        const uint32_t Bbuf = sbB + (kc & 1) * (NPACK * 128);

#pragma unroll
        for (int ks = 0; ks < 4; ks++) {
            // ---- A fragments via ldmatrix.x4 ----
            uint32_t af[2][4];
#pragma unroll
            for (int mf = 0; mf < 2; mf++) {
                if (mf < nmf) {
                    uint32_t row = (uint32_t)(wm * 16 * nmf + mf * 16 + (lid & 15));
                    uint32_t off = row * 128 + (uint32_t)(ks * 32 + ((lid >> 4) & 1) * 16);
                    uint32_t addr = sbA16 + (off ^ ((off >> 3) & 0x70));
                    asm volatile("ldmatrix.sync.aligned.m8n8.x4.shared.b16 {%0,%1,%2,%3}, [%4];"
                                 : "=r"(af[mf][0]), "=r"(af[mf][1]),
                                   "=r"(af[mf][2]), "=r"(af[mf][3]) : "r"(addr));
                }
            }
            // ---- B fragments: x4 per adjacent n-frag pair ----
#pragma unroll
            for (int np = 0; np < 5; np++) {
                const int nf = np * 2;
                int row = wn * 88 + (nf + ((lid >> 4) & 1)) * 8 + (lid & 7);
                uint32_t off = (uint32_t)(row * 128 + ks * 32 + ((lid >> 3) & 1) * 16);
                uint32_t addr = Bbuf + (off ^ ((off >> 3) & 0x70));
                uint32_t b0, b1, b2, b3;
                asm volatile("ldmatrix.sync.aligned.m8n8.x4.shared.b16 {%0,%1,%2,%3}, [%4];"
                             : "=r"(b0), "=r"(b1), "=r"(b2), "=r"(b3) : "r"(addr));
#pragma unroll
                for (int mf = 0; mf < 2; mf++) {
                    if (mf < nmf) {
                        asm volatile(
                            "mma.sync.aligned.m16n8k16.row.col.f32.f16.f16.f32 "
                            "{%0,%1,%2,%3},{%4,%5,%6,%7},{%8,%9},{%0,%1,%2,%3};"
                            : "+f"(acc[mf][nf][0]), "+f"(acc[mf][nf][1]),
                              "+f"(acc[mf][nf][2]), "+f"(acc[mf][nf][3])
                            : "r"(af[mf][0]), "r"(af[mf][1]), "r"(af[mf][2]), "r"(af[mf][3]),
                              "r"(b0), "r"(b1));
                        asm volatile(
                            "mma.sync.aligned.m16n8k16.row.col.f32.f16.f16.f32 "
                            "{%0,%1,%2,%3},{%4,%5,%6,%7},{%8,%9},{%0,%1,%2,%3};"
                            : "+f"(acc[mf][nf + 1][0]), "+f"(acc[mf][nf + 1][1]),
                              "+f"(acc[mf][nf + 1][2]), "+f"(acc[mf][nf + 1][3])
                            : "r"(af[mf][0]), "r"(af[mf][1]), "r"(af[mf][2]), "r"(af[mf][3]),
                              "r"(b2), "r"(b3));
                    }
                }
            }
            if (wn != 3) {   // ---- nf=10; wn==3 cols 344-351 = pad, skip ----
                const int nf = 10;
                int row = wn * 88 + nf * 8 + (lid & 7);
                uint32_t off = (uint32_t)(row * 128 + ks * 32 + ((lid >> 3) & 1) * 16);
                uint32_t addr = Bbuf + (off ^ ((off >> 3) & 0x70));
                uint32_t b0, b1;
                asm volatile("ldmatrix.sync.aligned.m8n8.x2.shared.b16 {%0,%1}, [%2];"
                             : "=r"(b0), "=r"(b1) : "r"(addr));
#pragma unroll
                for (int mf = 0; mf < 2; mf++) {
                    if (mf < nmf) {
                        asm volatile(
                            "mma.sync.aligned.m16n8k16.row.col.f32.f16.f16.f32 "
                            "{%0,%1,%2,%3},{%4,%5,%6,%7},{%8,%9},{%0,%1,%2,%3};"
                            : "+f"(acc[mf][nf][0]), "+f"(acc[mf][nf][1]),
                              "+f"(acc[mf][nf][2]), "+f"(acc[mf][nf][3])
                            : "r"(af[mf][0]), "r"(af[mf][1]), "r"(af[mf][2]), "r"(af[mf][3]),
                              "r"(b0), "r"(b1));
                    }
                }
            }
        }
    }

    // =========================================================================
    // Epilogue: stage tile outputs in smem, then fully coalesced global writes.
    // =========================================================================
    __syncthreads();          // all MMAs done; GEMM smem region reusable

    // ---- zero the scores staging (masked class cols stay 0) ----
    for (int i = tid; i < arows * NSC; i += THREADS) {
        int r = i / NSC, c = i - r * NSC;
        s_stage[r * STRIDE_W + 324 + c] = 0.0f;
    }
    __syncthreads();

    // ---- scatter accumulators (+bias) into staging ----
#pragma unroll
    for (int mf = 0; mf < 2; mf++) {
        if (mf < nmf) {
#pragma unroll
            for (int half = 0; half < 2; half++) {
                const int r = wm * 16 * nmf + mf * 16 + q + half * 8;  // local row
                float* srow = s_stage + r * STRIDE_W;
#pragma unroll
                for (int nf = 0; nf < 11; nf++) {
#pragma unroll
                    for (int e = 0; e < 2; e++) {
                        const int c = wn * 88 + nf * 8 + t * 2 + e;
                        float vv = acc[mf][nf][half * 2 + e] + s_bias[c];
                        if (c == 0)        srow[324 + 0] = vv;
                        else if (c <= 12)  srow[324 + 1 + c_sel[c - 1]] = vv;
                        else if (c <= 336) srow[c - 13] = vv;
                    }
                }
            }
        }
    }
    __syncthreads();

    // ---- coalesced scores write: contiguous block [mbase*81, +arows*81) ----
    {
        float* dst = out + (size_t)mbase * NSC;
        for (int i = tid; i < arows * NSC; i += THREADS) {
            int r = i / NSC, c = i - r * NSC;
            dst[i] = s_stage[r * STRIDE_W + 324 + c];
        }
    }
    // ---- coalesced bbox write: float4, rows of 324 floats = 81 float4 ----
    {
        float4* dst = (float4*)(out + (size_t)N_TOK * NSC + (size_t)mbase * NBB);
        for (int j = tid; j < arows * 81; j += THREADS) {
            int r = j / 81, c4 = j - r * 81;
            dst[j] = *(const float4*)(s_stage + r * STRIDE_W + c4 * 4);
        }
    }
}

// ---------------------------------------------------------------------------
// Launch
// ---------------------------------------------------------------------------
extern "C" void kernel_launch(void* const* d_in, const int* in_sizes, int n_in,
                              void* d_out, int out_size) {
    const float* x      = (const float*)d_in[0];
    const float* W_cls  = (const float*)d_in[1];
    const float* b_cls  = (const float*)d_in[2];
    const float* W_sem  = (const float*)d_in[3];
    const float* b_sem  = (const float*)d_in[4];
    const float* W_bbox = (const float*)d_in[5];
    const float* b_bbox = (const float*)d_in[6];
    const float* sem_m  = (const float*)d_in[7];
    float* out = (float*)d_out;

    cudaFuncSetAttribute(fpn_gemm, cudaFuncAttributeMaxDynamicSharedMemorySize, SM_TOTAL);

    prep_kernel<<<PREP_GRID, 256>>>(W_cls, b_cls, W_sem, b_sem, W_bbox, b_bbox, sem_m);
    fpn_gemm<<<GRID, THREADS, SM_TOTAL>>>(x, out);
}